// round 8
// baseline (speedup 1.0000x reference)
#include <cuda_runtime.h>
#include <cstdint>

#define COLS        16384
#define KSEL        64
#define NTHREADS    512
#define CAP         384
#define NBUF        4
#define CHUNK_BYTES 16384
#define CHUNK_F4    1024          // float4 per 16KB chunk
#define CHUNKS_ROW  4             // chunks per row
#define F4_PT       (CHUNK_F4 / NTHREADS)   // 2
#define ZERO_BYTES  4096
#define NGRID       456           // persistent CTAs (~3/SM)

// ---- dynamic smem layout (bytes) ----
#define OFF_BUF     0             // 4 x 16KB = 65536
#define OFF_ZERO    65536         // 4096
#define OFF_KEY     69632         // CAP*4 = 1536
#define OFF_IDX     71168         // CAP*4 = 1536
#define OFF_HIST    72704         // 256*4 = 1024
#define OFF_MBAR    73728         // 4 x 8 = 32
#define OFF_CNT     73760
#define OFF_SELBIN  73764
#define OFF_NEED    73768
#define OFF_STATUS  73772
#define OFF_PK      73776
#define OFF_LO      73780
#define OFF_HI      73784
#define SMEM_TOTAL  73856

// Monotonic uint key for float ordering.
__device__ __forceinline__ unsigned fkey(float f) {
    unsigned u = __float_as_uint(f);
    return u ^ ((unsigned)((int)u >> 31) | 0x80000000u);
}
__device__ __forceinline__ float key_to_float(unsigned k) {
    unsigned bits = (k & 0x80000000u) ? (k ^ 0x80000000u) : ~k;
    return __uint_as_float(bits);
}
__device__ __forceinline__ float key_to_pivot(unsigned k) {
    float f = key_to_float(k);
    if (f != f) f = (k & 0x80000000u) ? __uint_as_float(0x7F800000u)
                                      : __uint_as_float(0xFF800000u);
    return f;
}

__device__ __forceinline__ uint32_t smem_u32(const void* p) {
    uint32_t a;
    asm("{ .reg .u64 t; cvta.to.shared.u64 t, %1; cvt.u32.u64 %0, t; }"
        : "=r"(a) : "l"(p));
    return a;
}
__device__ __forceinline__ void mbar_init(uint32_t mbar, unsigned cnt) {
    asm volatile("mbarrier.init.shared.b64 [%0], %1;" :: "r"(mbar), "r"(cnt) : "memory");
}
__device__ __forceinline__ void mbar_expect_tx(uint32_t mbar, unsigned bytes) {
    asm volatile("mbarrier.arrive.expect_tx.shared.b64 _, [%0], %1;"
                 :: "r"(mbar), "r"(bytes) : "memory");
}
__device__ __forceinline__ void mbar_wait(uint32_t mbar, unsigned ph) {
    asm volatile(
        "{\n\t.reg .pred P1;\n\t"
        "WAIT_%=:\n\t"
        "mbarrier.try_wait.parity.acquire.cta.shared::cta.b64 P1, [%0], %1, 0x989680;\n\t"
        "@P1 bra.uni DONE_%=;\n\t"
        "bra.uni WAIT_%=;\n\t"
        "DONE_%=:\n\t}"
        :: "r"(mbar), "r"(ph) : "memory");
}
__device__ __forceinline__ void bulk_load(uint32_t dst_smem, const void* src,
                                          unsigned bytes, uint32_t mbar) {
    asm volatile(
        "cp.async.bulk.shared::cluster.global.mbarrier::complete_tx::bytes [%0], [%1], %2, [%3];"
        :: "r"(dst_smem), "l"(src), "r"(bytes), "r"(mbar) : "memory");
}
__device__ __forceinline__ void bulk_store(void* dst, uint32_t src_smem, unsigned bytes) {
    asm volatile("cp.async.bulk.global.shared::cta.bulk_group [%0], [%1], %2;"
                 :: "l"(dst), "r"(src_smem), "r"(bytes) : "memory");
}
__device__ __forceinline__ void bulk_commit() {
    asm volatile("cp.async.bulk.commit_group;" ::: "memory");
}
__device__ __forceinline__ void bulk_wait0() {
    asm volatile("cp.async.bulk.wait_group 0;" ::: "memory");
}

// Pathological fallback: LDG-based key-space bisection (never taken on normal data).
// Returns true if it dense-wrote the row (done); false if candidates are ready.
__device__ __noinline__ bool slow_path(const float* __restrict__ xrow,
                                       float* __restrict__ orow,
                                       unsigned* s_key, int* s_idx,
                                       int* s_cnt, unsigned* s_pk,
                                       unsigned* s_lo, unsigned* s_hi,
                                       int* s_status, int tid)
{
    const float4* vin = (const float4*)xrow;
    if (tid == 0) { *s_pk = fkey(2.4f); *s_lo = 0u; *s_hi = 0xFFFFFFFFu; }
    __syncthreads();
    for (;;) {
        float pivotf = key_to_pivot(*s_pk);
        if (tid == 0) *s_cnt = 0;
        __syncthreads();
        #pragma unroll 1
        for (int it = 0; it < COLS / (NTHREADS * 4); ++it) {
            int g = tid + it * NTHREADS;
            float4 v = vin[g];
            float m = fmaxf(fmaxf(v.x, v.y), fmaxf(v.z, v.w));
            if (m >= pivotf) {
                int base = g * 4;
                if (v.x >= pivotf) { int p = atomicAdd(s_cnt, 1); if (p < CAP) { s_key[p] = fkey(v.x); s_idx[p] = base + 0; } }
                if (v.y >= pivotf) { int p = atomicAdd(s_cnt, 1); if (p < CAP) { s_key[p] = fkey(v.y); s_idx[p] = base + 1; } }
                if (v.z >= pivotf) { int p = atomicAdd(s_cnt, 1); if (p < CAP) { s_key[p] = fkey(v.z); s_idx[p] = base + 2; } }
                if (v.w >= pivotf) { int p = atomicAdd(s_cnt, 1); if (p < CAP) { s_key[p] = fkey(v.w); s_idx[p] = base + 3; } }
            }
        }
        __syncthreads();
        int cc = *s_cnt;
        if (cc >= KSEL && cc <= CAP) return false;   // candidates ready
        if (tid == 0) {
            *s_status = 0;
            if (cc < KSEL) {
                *s_hi = *s_pk;
                unsigned step = (*s_pk - *s_lo) >> 1;
                if (step == 0) { *s_pk = *s_lo; *s_status = 2; }
                else           { *s_pk -= step; }
            } else {
                *s_lo = *s_pk;
                unsigned step = (*s_hi - *s_pk) >> 1;
                if (step == 0) { *s_status = 2; }
                else           { *s_pk += step; }
            }
        }
        __syncthreads();
        if (*s_status == 2) {
            // exact threshold == current pivot: dense masked write
            float Tf = key_to_pivot(*s_pk);
            if (tid == 0) bulk_wait0();   // zeros for this row must land first
            __syncthreads();
            float4* vout = (float4*)orow;
            #pragma unroll 1
            for (int it = 0; it < COLS / (NTHREADS * 4); ++it) {
                int g = tid + it * NTHREADS;
                float4 v = vin[g];
                float4 o;
                o.x = (v.x >= Tf) ? v.x : 0.0f;
                o.y = (v.y >= Tf) ? v.y : 0.0f;
                o.z = (v.z >= Tf) ? v.z : 0.0f;
                o.w = (v.w >= Tf) ? v.w : 0.0f;
                vout[g] = o;
            }
            __syncthreads();
            return true;
        }
    }
}

__global__ void __launch_bounds__(NTHREADS, 3)
sparsify_topk_kernel(const float* __restrict__ x, float* __restrict__ out, int rows)
{
    extern __shared__ __align__(1024) char smem[];
    const int tid = threadIdx.x;

    unsigned* s_key  = (unsigned*)(smem + OFF_KEY);
    int*      s_idx  = (int*)(smem + OFF_IDX);
    int*      s_hist = (int*)(smem + OFF_HIST);
    int*      s_cnt  = (int*)(smem + OFF_CNT);
    unsigned* s_selbin = (unsigned*)(smem + OFF_SELBIN);
    int*      s_need   = (int*)(smem + OFF_NEED);
    int*      s_status = (int*)(smem + OFF_STATUS);
    unsigned* s_pk = (unsigned*)(smem + OFF_PK);
    unsigned* s_lo = (unsigned*)(smem + OFF_LO);
    unsigned* s_hi = (unsigned*)(smem + OFF_HI);

    const uint32_t sbase = smem_u32(smem);
    const uint32_t zsm   = sbase + OFF_ZERO;

    if (tid == 0) {
        #pragma unroll
        for (int s = 0; s < NBUF; ++s) mbar_init(sbase + OFF_MBAR + 8 * s, 1);
        *s_cnt = 0;
    }
    for (int i = tid; i < ZERO_BYTES / 16; i += NTHREADS)
        ((float4*)(smem + OFF_ZERO))[i] = make_float4(0.f, 0.f, 0.f, 0.f);
    asm volatile("fence.proxy.async.shared::cta;" ::: "memory");
    __syncthreads();

    // rows assigned to this CTA: bid, bid+grid, ...
    const int bid = blockIdx.x;
    const int stride = (int)gridDim.x;
    const int nrows_cta = (rows > bid) ? (rows - bid + stride - 1) / stride : 0;
    const int tot_chunks = nrows_cta * CHUNKS_ROW;

    // issue a global chunk g: row j=g/4, chunk c=g%4, buffer slot c
    auto issue = [&](int g) {
        int j = g >> 2, c = g & 3;
        size_t row = (size_t)(bid + j * stride);
        uint32_t mb = sbase + OFF_MBAR + 8 * c;
        mbar_expect_tx(mb, CHUNK_BYTES);
        bulk_load(sbase + OFF_BUF + c * CHUNK_BYTES,
                  x + row * COLS + (size_t)c * (CHUNK_F4 * 4), CHUNK_BYTES, mb);
    };

    int gp = 0;
    if (tid == 0)
        for (; gp < tot_chunks && gp < NBUF - 1; ++gp) issue(gp);
    gp = (tot_chunks < NBUF - 1) ? tot_chunks : NBUF - 1;   // uniform across threads

    for (int j = 0; j < nrows_cta; ++j) {
        const int r = bid + j * stride;
        const float* xrow = x + (size_t)r * COLS;
        float* orow = out + (size_t)r * COLS;

        if (tid == 0) {
            // async zero-fill of this output row (16 x 4KB)
            #pragma unroll 1
            for (int i = 0; i < COLS * 4 / ZERO_BYTES; ++i)
                bulk_store(orow + i * (ZERO_BYTES / 4), zsm, ZERO_BYTES);
            bulk_commit();
        }

        const unsigned par = (unsigned)(j & 1);
        #pragma unroll
        for (int c = 0; c < CHUNKS_ROW; ++c) {
            mbar_wait(sbase + OFF_MBAR + 8 * c, par);
            const float4* buf = (const float4*)(smem + OFF_BUF + c * CHUNK_BYTES);
            const int cbase = c * (CHUNK_F4 * 4);
            #pragma unroll
            for (int t = 0; t < F4_PT; ++t) {
                int gidx = tid + t * NTHREADS;
                float4 v = buf[gidx];
                float m = fmaxf(fmaxf(v.x, v.y), fmaxf(v.z, v.w));
                if (m >= 2.4f) {
                    int base = cbase + gidx * 4;
                    if (v.x >= 2.4f) { int p = atomicAdd(s_cnt, 1); if (p < CAP) { s_key[p] = fkey(v.x); s_idx[p] = base + 0; } }
                    if (v.y >= 2.4f) { int p = atomicAdd(s_cnt, 1); if (p < CAP) { s_key[p] = fkey(v.y); s_idx[p] = base + 1; } }
                    if (v.z >= 2.4f) { int p = atomicAdd(s_cnt, 1); if (p < CAP) { s_key[p] = fkey(v.z); s_idx[p] = base + 2; } }
                    if (v.w >= 2.4f) { int p = atomicAdd(s_cnt, 1); if (p < CAP) { s_key[p] = fkey(v.w); s_idx[p] = base + 3; } }
                }
            }
            __syncthreads();   // slot c fully consumed by all threads
            if (tid == 0 && gp < tot_chunks) issue(gp);
            ++gp;              // uniform
        }

        int cc = *s_cnt;
        if (cc < KSEL || cc > CAP) {
            if (slow_path(xrow, orow, s_key, s_idx, s_cnt, s_pk, s_lo, s_hi, s_status, tid)) {
                if (tid == 0) *s_cnt = 0;
                __syncthreads();
                continue;
            }
            cc = *s_cnt;
        }

        // ---- exact selection: 4-level radix select over candidates ----
        unsigned prefix = 0;
        int need = KSEL;
        #pragma unroll
        for (int level = 0; level < 4; ++level) {
            const int shift = 24 - 8 * level;
            if (tid < 256) s_hist[tid] = 0;
            __syncthreads();
            for (int i = tid; i < cc; i += NTHREADS) {
                unsigned k = s_key[i];
                bool match = (level == 0) || ((k >> (shift + 8)) == (prefix >> (shift + 8)));
                if (match) atomicAdd(&s_hist[(k >> shift) & 255], 1);
            }
            __syncthreads();
            if (tid < 32) {
                int base = 255 - 8 * tid;
                int s0 = 0;
                #pragma unroll
                for (int jj = 0; jj < 8; ++jj) s0 += s_hist[base - jj];
                int inc = s0;
                #pragma unroll
                for (int off = 1; off < 32; off <<= 1) {
                    int o = __shfl_up_sync(0xFFFFFFFFu, inc, off);
                    if (tid >= off) inc += o;
                }
                int excl = inc - s0;
                unsigned ball = __ballot_sync(0xFFFFFFFFu, (excl < need) && (need <= inc));
                int lane = __ffs(ball) - 1;
                if (tid == lane) {
                    int cum = excl;
                    #pragma unroll
                    for (int jj = 0; jj < 8; ++jj) {
                        int h = s_hist[base - jj];
                        if (cum + h >= need) { *s_selbin = (unsigned)(base - jj); *s_need = need - cum; break; }
                        cum += h;
                    }
                }
            }
            __syncthreads();
            prefix |= (*s_selbin << shift);
            need = *s_need;
            __syncthreads();
        }
        unsigned T = prefix;

        // zeros for this row must be in GMEM before the scatter overwrites
        if (tid == 0) bulk_wait0();
        __syncthreads();

        for (int i = tid; i < cc; i += NTHREADS) {
            unsigned k = s_key[i];
            if (k >= T) orow[s_idx[i]] = key_to_float(k);
        }

        if (tid == 0) *s_cnt = 0;
        __syncthreads();
    }
}

extern "C" void kernel_launch(void* const* d_in, const int* in_sizes, int n_in,
                              void* d_out, int out_size) {
    const float* x = (const float*)d_in[0];
    float* out = (float*)d_out;
    int rows = in_sizes[0] / COLS;
    cudaFuncSetAttribute(sparsify_topk_kernel,
                         cudaFuncAttributeMaxDynamicSharedMemorySize, SMEM_TOTAL);
    sparsify_topk_kernel<<<NGRID, NTHREADS, SMEM_TOTAL>>>(x, out, rows);
}

// round 10
// speedup vs baseline: 1.0089x; 1.0089x over previous
#include <cuda_runtime.h>
#include <cstdint>

#define COLS        16384
#define KSEL        64
#define NTHREADS    512
#define CAP         256
#define NBUF        3
#define CHUNK_BYTES 16384
#define CHUNK_F4    1024          // float4 per 16KB chunk
#define CHUNKS_ROW  4             // chunks per row
#define F4_PT       (CHUNK_F4 / NTHREADS)   // 2
#define ZERO_BYTES  4096
#define NGRID       592           // persistent CTAs (4/SM x 148)

// ---- dynamic smem layout (bytes) ----
#define OFF_BUF     0             // 3 x 16KB = 49152
#define OFF_ZERO    49152         // 4096
#define OFF_KEY     53248         // CAP*4 = 1024
#define OFF_IDX     54272         // 1024
#define OFF_HIST    55296         // 1024
#define OFF_MBAR    56320         // 3 x 8 = 24
#define OFF_CNT     56352
#define OFF_SELBIN  56356
#define OFF_NEED    56360
#define OFF_STATUS  56364
#define OFF_PK      56368
#define OFF_LO      56372
#define OFF_HI      56376
#define SMEM_TOTAL  56448

// Monotonic uint key for float ordering.
__device__ __forceinline__ unsigned fkey(float f) {
    unsigned u = __float_as_uint(f);
    return u ^ ((unsigned)((int)u >> 31) | 0x80000000u);
}
__device__ __forceinline__ float key_to_float(unsigned k) {
    unsigned bits = (k & 0x80000000u) ? (k ^ 0x80000000u) : ~k;
    return __uint_as_float(bits);
}
__device__ __forceinline__ float key_to_pivot(unsigned k) {
    float f = key_to_float(k);
    if (f != f) f = (k & 0x80000000u) ? __uint_as_float(0x7F800000u)
                                      : __uint_as_float(0xFF800000u);
    return f;
}

__device__ __forceinline__ uint32_t smem_u32(const void* p) {
    uint32_t a;
    asm("{ .reg .u64 t; cvta.to.shared.u64 t, %1; cvt.u32.u64 %0, t; }"
        : "=r"(a) : "l"(p));
    return a;
}
__device__ __forceinline__ void mbar_init(uint32_t mbar, unsigned cnt) {
    asm volatile("mbarrier.init.shared.b64 [%0], %1;" :: "r"(mbar), "r"(cnt) : "memory");
}
__device__ __forceinline__ void mbar_expect_tx(uint32_t mbar, unsigned bytes) {
    asm volatile("mbarrier.arrive.expect_tx.shared.b64 _, [%0], %1;"
                 :: "r"(mbar), "r"(bytes) : "memory");
}
__device__ __forceinline__ void mbar_wait(uint32_t mbar, unsigned ph) {
    asm volatile(
        "{\n\t.reg .pred P1;\n\t"
        "WAIT_%=:\n\t"
        "mbarrier.try_wait.parity.acquire.cta.shared::cta.b64 P1, [%0], %1, 0x989680;\n\t"
        "@P1 bra.uni DONE_%=;\n\t"
        "bra.uni WAIT_%=;\n\t"
        "DONE_%=:\n\t}"
        :: "r"(mbar), "r"(ph) : "memory");
}
__device__ __forceinline__ void bulk_load(uint32_t dst_smem, const void* src,
                                          unsigned bytes, uint32_t mbar) {
    asm volatile(
        "cp.async.bulk.shared::cluster.global.mbarrier::complete_tx::bytes [%0], [%1], %2, [%3];"
        :: "r"(dst_smem), "l"(src), "r"(bytes), "r"(mbar) : "memory");
}
__device__ __forceinline__ void bulk_store(void* dst, uint32_t src_smem, unsigned bytes) {
    asm volatile("cp.async.bulk.global.shared::cta.bulk_group [%0], [%1], %2;"
                 :: "l"(dst), "r"(src_smem), "r"(bytes) : "memory");
}
__device__ __forceinline__ void bulk_commit() {
    asm volatile("cp.async.bulk.commit_group;" ::: "memory");
}
__device__ __forceinline__ void bulk_wait0() {
    asm volatile("cp.async.bulk.wait_group 0;" ::: "memory");
}

// Pathological fallback: LDG-based key-space bisection (never taken on normal data).
// Returns true if it dense-wrote the row (done); false if candidates are ready.
__device__ __noinline__ bool slow_path(const float* __restrict__ xrow,
                                       float* __restrict__ orow,
                                       unsigned* s_key, int* s_idx,
                                       int* s_cnt, unsigned* s_pk,
                                       unsigned* s_lo, unsigned* s_hi,
                                       int* s_status, int tid)
{
    const float4* vin = (const float4*)xrow;
    if (tid == 0) { *s_pk = fkey(2.4f); *s_lo = 0u; *s_hi = 0xFFFFFFFFu; }
    __syncthreads();
    for (;;) {
        float pivotf = key_to_pivot(*s_pk);
        if (tid == 0) *s_cnt = 0;
        __syncthreads();
        #pragma unroll 1
        for (int it = 0; it < COLS / (NTHREADS * 4); ++it) {
            int g = tid + it * NTHREADS;
            float4 v = vin[g];
            float m = fmaxf(fmaxf(v.x, v.y), fmaxf(v.z, v.w));
            if (m >= pivotf) {
                int base = g * 4;
                if (v.x >= pivotf) { int p = atomicAdd(s_cnt, 1); if (p < CAP) { s_key[p] = fkey(v.x); s_idx[p] = base + 0; } }
                if (v.y >= pivotf) { int p = atomicAdd(s_cnt, 1); if (p < CAP) { s_key[p] = fkey(v.y); s_idx[p] = base + 1; } }
                if (v.z >= pivotf) { int p = atomicAdd(s_cnt, 1); if (p < CAP) { s_key[p] = fkey(v.z); s_idx[p] = base + 2; } }
                if (v.w >= pivotf) { int p = atomicAdd(s_cnt, 1); if (p < CAP) { s_key[p] = fkey(v.w); s_idx[p] = base + 3; } }
            }
        }
        __syncthreads();
        int cc = *s_cnt;
        if (cc >= KSEL && cc <= CAP) return false;   // candidates ready
        if (tid == 0) {
            *s_status = 0;
            if (cc < KSEL) {
                *s_hi = *s_pk;
                unsigned step = (*s_pk - *s_lo) >> 1;
                if (step == 0) { *s_pk = *s_lo; *s_status = 2; }
                else           { *s_pk -= step; }
            } else {
                *s_lo = *s_pk;
                unsigned step = (*s_hi - *s_pk) >> 1;
                if (step == 0) { *s_status = 2; }
                else           { *s_pk += step; }
            }
        }
        __syncthreads();
        if (*s_status == 2) {
            // exact threshold == current pivot: dense masked write
            float Tf = key_to_pivot(*s_pk);
            if (tid == 0) bulk_wait0();   // zeros for this row must land first
            __syncthreads();
            float4* vout = (float4*)orow;
            #pragma unroll 1
            for (int it = 0; it < COLS / (NTHREADS * 4); ++it) {
                int g = tid + it * NTHREADS;
                float4 v = vin[g];
                float4 o;
                o.x = (v.x >= Tf) ? v.x : 0.0f;
                o.y = (v.y >= Tf) ? v.y : 0.0f;
                o.z = (v.z >= Tf) ? v.z : 0.0f;
                o.w = (v.w >= Tf) ? v.w : 0.0f;
                vout[g] = o;
            }
            __syncthreads();
            return true;
        }
    }
}

__global__ void __launch_bounds__(NTHREADS, 4)
sparsify_topk_kernel(const float* __restrict__ x, float* __restrict__ out, int rows)
{
    extern __shared__ __align__(1024) char smem[];
    const int tid = threadIdx.x;

    unsigned* s_key  = (unsigned*)(smem + OFF_KEY);
    int*      s_idx  = (int*)(smem + OFF_IDX);
    int*      s_hist = (int*)(smem + OFF_HIST);
    int*      s_cnt  = (int*)(smem + OFF_CNT);
    unsigned* s_selbin = (unsigned*)(smem + OFF_SELBIN);
    int*      s_need   = (int*)(smem + OFF_NEED);
    int*      s_status = (int*)(smem + OFF_STATUS);
    unsigned* s_pk = (unsigned*)(smem + OFF_PK);
    unsigned* s_lo = (unsigned*)(smem + OFF_LO);
    unsigned* s_hi = (unsigned*)(smem + OFF_HI);

    const uint32_t sbase = smem_u32(smem);
    const uint32_t zsm   = sbase + OFF_ZERO;

    if (tid == 0) {
        #pragma unroll
        for (int s = 0; s < NBUF; ++s) mbar_init(sbase + OFF_MBAR + 8 * s, 1);
        *s_cnt = 0;
    }
    for (int i = tid; i < ZERO_BYTES / 16; i += NTHREADS)
        ((float4*)(smem + OFF_ZERO))[i] = make_float4(0.f, 0.f, 0.f, 0.f);
    asm volatile("fence.proxy.async.shared::cta;" ::: "memory");
    __syncthreads();

    // rows assigned to this CTA: bid, bid+grid, ...
    const int bid = blockIdx.x;
    const int stride = (int)gridDim.x;
    const int nrows_cta = (rows > bid) ? (rows - bid + stride - 1) / stride : 0;
    const int tot_chunks = nrows_cta * CHUNKS_ROW;

    // issue global chunk g: row j=g/4, chunk c=g&3, ring slot g%3
    auto issue = [&](int g) {
        int j = g >> 2, c = g & 3, slot = g % NBUF;
        size_t row = (size_t)(bid + j * stride);
        uint32_t mb = sbase + OFF_MBAR + 8 * slot;
        mbar_expect_tx(mb, CHUNK_BYTES);
        bulk_load(sbase + OFF_BUF + slot * CHUNK_BYTES,
                  x + row * COLS + (size_t)c * (CHUNK_F4 * 4), CHUNK_BYTES, mb);
    };

    int npre = (tot_chunks < NBUF) ? tot_chunks : NBUF;
    if (tid == 0)
        for (int g = 0; g < npre; ++g) issue(g);
    int gp = npre;   // next chunk to issue (uniform)

    for (int j = 0; j < nrows_cta; ++j) {
        const int r = bid + j * stride;
        const float* xrow = x + (size_t)r * COLS;
        float* orow = out + (size_t)r * COLS;

        if (tid == 0) {
            // async zero-fill of this output row (16 x 4KB)
            #pragma unroll 1
            for (int i = 0; i < COLS * 4 / ZERO_BYTES; ++i)
                bulk_store(orow + i * (ZERO_BYTES / 4), zsm, ZERO_BYTES);
            bulk_commit();
        }

        #pragma unroll
        for (int c = 0; c < CHUNKS_ROW; ++c) {
            const int g = j * CHUNKS_ROW + c;
            const int slot = g % NBUF;
            const unsigned par = (unsigned)((g / NBUF) & 1);
            mbar_wait(sbase + OFF_MBAR + 8 * slot, par);
            const float4* buf = (const float4*)(smem + OFF_BUF + slot * CHUNK_BYTES);
            const int cbase = c * (CHUNK_F4 * 4);
            #pragma unroll
            for (int t = 0; t < F4_PT; ++t) {
                int gidx = tid + t * NTHREADS;
                float4 v = buf[gidx];
                float m = fmaxf(fmaxf(v.x, v.y), fmaxf(v.z, v.w));
                if (m >= 2.4f) {
                    int base = cbase + gidx * 4;
                    if (v.x >= 2.4f) { int p = atomicAdd(s_cnt, 1); if (p < CAP) { s_key[p] = fkey(v.x); s_idx[p] = base + 0; } }
                    if (v.y >= 2.4f) { int p = atomicAdd(s_cnt, 1); if (p < CAP) { s_key[p] = fkey(v.y); s_idx[p] = base + 1; } }
                    if (v.z >= 2.4f) { int p = atomicAdd(s_cnt, 1); if (p < CAP) { s_key[p] = fkey(v.z); s_idx[p] = base + 2; } }
                    if (v.w >= 2.4f) { int p = atomicAdd(s_cnt, 1); if (p < CAP) { s_key[p] = fkey(v.w); s_idx[p] = base + 3; } }
                }
            }
            __syncthreads();   // slot fully consumed by all threads
            if (tid == 0 && gp < tot_chunks) issue(gp);
            ++gp;              // uniform
        }

        int cc = *s_cnt;
        if (cc < KSEL || cc > CAP) {
            if (slow_path(xrow, orow, s_key, s_idx, s_cnt, s_pk, s_lo, s_hi, s_status, tid)) {
                if (tid == 0) *s_cnt = 0;
                __syncthreads();
                continue;
            }
            cc = *s_cnt;
        }

        // ---- exact selection: 4-level radix select over candidates ----
        unsigned prefix = 0;
        int need = KSEL;
        #pragma unroll
        for (int level = 0; level < 4; ++level) {
            const int shift = 24 - 8 * level;
            if (tid < 256) s_hist[tid] = 0;
            __syncthreads();
            for (int i = tid; i < cc; i += NTHREADS) {
                unsigned k = s_key[i];
                bool match = (level == 0) || ((k >> (shift + 8)) == (prefix >> (shift + 8)));
                if (match) atomicAdd(&s_hist[(k >> shift) & 255], 1);
            }
            __syncthreads();
            if (tid < 32) {
                int base = 255 - 8 * tid;
                int s0 = 0;
                #pragma unroll
                for (int jj = 0; jj < 8; ++jj) s0 += s_hist[base - jj];
                int inc = s0;
                #pragma unroll
                for (int off = 1; off < 32; off <<= 1) {
                    int o = __shfl_up_sync(0xFFFFFFFFu, inc, off);
                    if (tid >= off) inc += o;
                }
                int excl = inc - s0;
                unsigned ball = __ballot_sync(0xFFFFFFFFu, (excl < need) && (need <= inc));
                int lane = __ffs(ball) - 1;
                if (tid == lane) {
                    int cum = excl;
                    #pragma unroll
                    for (int jj = 0; jj < 8; ++jj) {
                        int h = s_hist[base - jj];
                        if (cum + h >= need) { *s_selbin = (unsigned)(base - jj); *s_need = need - cum; break; }
                        cum += h;
                    }
                }
            }
            __syncthreads();
            prefix |= (*s_selbin << shift);
            need = *s_need;
            __syncthreads();
        }
        unsigned T = prefix;

        // zeros for this row must be in GMEM before the scatter overwrites
        if (tid == 0) bulk_wait0();
        __syncthreads();

        for (int i = tid; i < cc; i += NTHREADS) {
            unsigned k = s_key[i];
            if (k >= T) orow[s_idx[i]] = key_to_float(k);
        }

        if (tid == 0) *s_cnt = 0;
        __syncthreads();
    }
}

extern "C" void kernel_launch(void* const* d_in, const int* in_sizes, int n_in,
                              void* d_out, int out_size) {
    const float* x = (const float*)d_in[0];
    float* out = (float*)d_out;
    int rows = in_sizes[0] / COLS;
    cudaFuncSetAttribute(sparsify_topk_kernel,
                         cudaFuncAttributeMaxDynamicSharedMemorySize, SMEM_TOTAL);
    sparsify_topk_kernel<<<NGRID, NTHREADS, SMEM_TOTAL>>>(x, out, rows);
}